// round 11
// baseline (speedup 1.0000x reference)
#include <cuda_runtime.h>
#include <cuda_bf16.h>

#define SDIM 128
#define CDIM 8
#define ROWS_PER_SLAB 16384          // 128*128 (d,h) rows per channel slab
#define NPACK_BLOCKS 2048            // pack: 256 words per block
#define NERODE (1u << 17)            // erode: one row per thread
#define NBLK2 16384                  // loss: 2^22 tasks (4 voxels each) / 256

__device__ double g_sum;
__device__ double g_cnt;
__device__ unsigned g_done;
__device__ uint4 g_pack[8 * ROWS_PER_SLAB];   // 2 MB targets bitmask (1 uint4 = 128-voxel row)
__device__ uint4 g_er[8 * ROWS_PER_SLAB];     // 2 MB eroded bitmask

// ---------- 128-bit row ops ----------
__device__ __forceinline__ uint4 band(uint4 a, uint4 b) {
    return make_uint4(a.x & b.x, a.y & b.y, a.z & b.z, a.w & b.w);
}
__device__ __forceinline__ uint4 shl1(uint4 a) {
    return make_uint4(a.x << 1, __funnelshift_l(a.x, a.y, 1),
                      __funnelshift_l(a.y, a.z, 1), __funnelshift_l(a.z, a.w, 1));
}
__device__ __forceinline__ uint4 shr1(uint4 a) {
    return make_uint4(__funnelshift_r(a.x, a.y, 1), __funnelshift_r(a.y, a.z, 1),
                      __funnelshift_r(a.z, a.w, 1), a.w >> 1);
}
__device__ __forceinline__ uint4 shl2(uint4 a) {
    return make_uint4(a.x << 2, __funnelshift_l(a.x, a.y, 2),
                      __funnelshift_l(a.y, a.z, 2), __funnelshift_l(a.z, a.w, 2));
}
__device__ __forceinline__ uint4 shr2(uint4 a) {
    return make_uint4(__funnelshift_r(a.x, a.y, 2), __funnelshift_r(a.y, a.z, 2),
                      __funnelshift_r(a.z, a.w, 2), a.w >> 2);
}
__device__ __forceinline__ unsigned pick(uint4 v, int s) {
    unsigned lo = (s & 1) ? v.y : v.x;
    unsigned hi = (s & 1) ? v.w : v.z;
    return (s & 2) ? hi : lo;
}

// ---------- Pass 1: bit-pack targets (coalesced loads + smem nibble transpose) ----------
// Block = 256 threads -> 256 words = 8192 floats, contiguous. All words of a
// block belong to one slab (65536 words/slab, 256/block).
__global__ void __launch_bounds__(256)
pack_kernel(const float* __restrict__ targets,
            const unsigned int* __restrict__ mask)
{
    if (blockIdx.x == 0 && threadIdx.x == 0) { g_sum = 0.0; g_cnt = 0.0; g_done = 0u; }

    unsigned p = blockIdx.x;
    int slab = p >> 8;                               // 0..7 (block-uniform)
    int b = slab >> 2;
    int ch = ((slab & 3) << 1) + 1;
    if (mask[b * CDIM + ch] == 0u) return;           // inactive: never read

    __shared__ __align__(8) unsigned char nib[2048];
    unsigned t = threadIdx.x;
    size_t base = ((size_t)(b * CDIM + ch) << 21) + ((size_t)(p & 255u) << 13);
    const float4* src = (const float4*)(targets + base);

    #pragma unroll
    for (int i = 0; i < 8; ++i) {                    // coalesced: lanes adjacent
        float4 v = __ldg(src + i * 256 + t);
        unsigned n = (v.x > 0.5f ? 1u : 0u) | (v.y > 0.5f ? 2u : 0u)
                   | (v.z > 0.5f ? 4u : 0u) | (v.w > 0.5f ? 8u : 0u);
        nib[i * 256 + t] = (unsigned char)n;
    }
    __syncthreads();

    uint2 q = *(const uint2*)(nib + 8 * t);          // 8 nibbles (bytes) for this word
    unsigned x = q.x; x = (x | (x >> 4)) & 0x00FF00FFu; x = (x | (x >> 8)) & 0x0000FFFFu;
    unsigned y = q.y; y = (y | (y >> 4)) & 0x00FF00FFu; y = (y | (y >> 8)) & 0x0000FFFFu;
    ((unsigned*)g_pack)[p * 256u + t] = x | (y << 16);
}

// ---------- Pass 1.5: double 6-conn erosion of the bitmask (one row per thread) ----------
__global__ void __launch_bounds__(256)
erode_kernel(const unsigned int* __restrict__ mask)
{
    unsigned j = blockIdx.x * 256u + threadIdx.x;    // < 2^17
    int slab = j >> 14;
    int b = slab >> 2;
    int ch = ((slab & 3) << 1) + 1;
    if (mask[b * CDIM + ch] == 0u) return;

    int rr = j & (ROWS_PER_SLAB - 1);
    int d = rr >> 7, h = rr & 127;

    uint4 e = make_uint4(0, 0, 0, 0);
    if (d >= 2 && d <= 125 && h >= 2 && h <= 125) {
        const uint4* pk = g_pack + slab * ROWS_PER_SLAB;
        uint4 m00 = __ldg(pk + rr);
        uint4 a0 = __ldg(pk + rr + 256), a1 = __ldg(pk + rr - 256);
        uint4 a2 = __ldg(pk + rr + 2),   a3 = __ldg(pk + rr - 2);
        uint4 a4 = __ldg(pk + rr + 129), a5 = __ldg(pk + rr + 127);
        uint4 a6 = __ldg(pk + rr - 127), a7 = __ldg(pk + rr - 129);
        uint4 a8 = __ldg(pk + rr + 128), a9 = __ldg(pk + rr - 128);
        uint4 aA = __ldg(pk + rr + 1),   aB = __ldg(pk + rr - 1);

        uint4 R = band(band(band(a0, a1), band(a2, a3)),
                       band(band(a4, a5), band(a6, a7)));
        uint4 q = band(band(a8, a9), band(aA, aB));
        uint4 u = band(m00, q);
        e = band(band(band(R, m00), u), band(shl1(u), shr1(u)));
        e = band(e, band(shl2(m00), shr2(m00)));
    }
    g_er[slab * ROWS_PER_SLAB + rr] = e;
}

// ---------- Pass 2: BCE + weights + reduction + fused finalize ----------
// One thread = 4 consecutive voxels; warp = exactly one 128-voxel row (coalesced).
__global__ void __launch_bounds__(256)
loss_kernel(const float* __restrict__ logits,
            const unsigned int* __restrict__ mask,
            const float* __restrict__ spatial,
            float* __restrict__ out)
{
    unsigned task = blockIdx.x * 256u + threadIdx.x;   // < 2^22
    int slab = task >> 19;                             // warp-uniform
    int b = slab >> 2;
    int ch = ((slab & 3) << 1) + 1;

    float vsum = 0.0f, csum = 0.0f;

    if (mask[b * CDIM + ch] != 0u) {                   // warp-uniform L1 scalar
        int lane = task & 31;
        int rr = (task >> 5) & (ROWS_PER_SLAB - 1);    // d*128 + h (warp-uniform)
        int w0 = lane << 2;

        size_t lix = ((size_t)(b * CDIM + ch) << 21) + ((size_t)rr << 7) + w0;
        unsigned six = ((unsigned)b << 21) + ((unsigned)rr << 7) + w0;
        float4 lg = __ldg((const float4*)(logits + lix));    // coalesced
        float4 sm = __ldg((const float4*)(spatial + six));   // coalesced
        uint4 m00 = __ldg(g_pack + slab * ROWS_PER_SLAB + rr);  // broadcast
        uint4 e00 = __ldg(g_er   + slab * ROWS_PER_SLAB + rr);  // broadcast

        int sh = w0 & 31;
        unsigned tw = (pick(m00, lane >> 3) >> sh) & 0xFu;
        unsigned eb = (pick(e00, lane >> 3) >> sh) & 0xFu;
        unsigned bbits = tw & ~eb;                     // boundary bits

        #pragma unroll
        for (int k = 0; k < 4; ++k) {
            float l = (k == 0) ? lg.x : (k == 1) ? lg.y : (k == 2) ? lg.z : lg.w;
            float s = (k == 0) ? sm.x : (k == 1) ? sm.y : (k == 2) ? sm.z : sm.w;
            unsigned tb = (tw >> k) & 1u;
            // max(l,0) - l*t == max(sflip, 0) with sflip = t ? -l : l
            float sflip = __uint_as_float(__float_as_uint(l) ^ (tb << 31));
            float u = __expf(-fabsf(l));
            float bce = fmaxf(sflip, 0.0f) + __logf(1.0f + u);
            float wgt = ((bbits >> k) & 1u) ? 5.0f : 1.0f;
            vsum += bce * wgt * s;
            csum += s;
        }
    }

    // warp reduce
    #pragma unroll
    for (int off = 16; off > 0; off >>= 1) {
        vsum += __shfl_down_sync(0xFFFFFFFFu, vsum, off);
        csum += __shfl_down_sync(0xFFFFFFFFu, csum, off);
    }
    __shared__ float s_v[8], s_c[8];
    int lane = threadIdx.x & 31, wid = threadIdx.x >> 5;
    if (lane == 0) { s_v[wid] = vsum; s_c[wid] = csum; }
    __syncthreads();
    if (wid == 0) {
        vsum = (lane < 8) ? s_v[lane] : 0.0f;
        csum = (lane < 8) ? s_c[lane] : 0.0f;
        #pragma unroll
        for (int off = 4; off > 0; off >>= 1) {
            vsum += __shfl_down_sync(0xFFFFFFFFu, vsum, off);
            csum += __shfl_down_sync(0xFFFFFFFFu, csum, off);
        }
        if (lane == 0) {
            if (vsum != 0.0f) atomicAdd(&g_sum, (double)vsum);
            if (csum != 0.0f) atomicAdd(&g_cnt, (double)csum);
            __threadfence();
            unsigned ticket = atomicAdd(&g_done, 1u);
            if (ticket == NBLK2 - 1u) {              // last block finalizes
                double n = g_cnt;
                double s = g_sum;
                out[0] = (n > 0.0) ? (float)(s / (n > 1.0 ? n : 1.0)) : 0.0f;
            }
        }
    }
}

extern "C" void kernel_launch(void* const* d_in, const int* in_sizes, int n_in,
                              void* d_out, int out_size) {
    const float*        logits  = (const float*)d_in[0];
    const float*        targets = (const float*)d_in[1];
    const unsigned int* mask    = (const unsigned int*)d_in[2];
    const float*        spatial = (const float*)d_in[3];
    float*              out     = (float*)d_out;

    pack_kernel<<<NPACK_BLOCKS, 256>>>(targets, mask);
    erode_kernel<<<NERODE / 256, 256>>>(mask);
    loss_kernel<<<NBLK2, 256>>>(logits, mask, spatial, out);
}

// round 12
// speedup vs baseline: 1.5859x; 1.5859x over previous
#include <cuda_runtime.h>
#include <cuda_bf16.h>

#define SDIM 128
#define CDIM 8
#define ROWS_PER_SLAB 16384          // 128*128 (d,h) rows per channel slab
#define NPACK_BLOCKS 2048            // pack: 256 words per block
#define NERODE (1u << 17)            // erode: one row per thread
#define NBLK2 4096                   // loss: 2^20 threads, 16 voxels each

__device__ double g_sum;
__device__ double g_cnt;
__device__ unsigned g_done;
__device__ uint4 g_pack[8 * ROWS_PER_SLAB];   // 2 MB targets bitmask (1 uint4 = 128-voxel row)
__device__ uint4 g_er[8 * ROWS_PER_SLAB];     // 2 MB eroded bitmask

// ---------- 128-bit row ops ----------
__device__ __forceinline__ uint4 band(uint4 a, uint4 b) {
    return make_uint4(a.x & b.x, a.y & b.y, a.z & b.z, a.w & b.w);
}
__device__ __forceinline__ uint4 shl1(uint4 a) {
    return make_uint4(a.x << 1, __funnelshift_l(a.x, a.y, 1),
                      __funnelshift_l(a.y, a.z, 1), __funnelshift_l(a.z, a.w, 1));
}
__device__ __forceinline__ uint4 shr1(uint4 a) {
    return make_uint4(__funnelshift_r(a.x, a.y, 1), __funnelshift_r(a.y, a.z, 1),
                      __funnelshift_r(a.z, a.w, 1), a.w >> 1);
}
__device__ __forceinline__ uint4 shl2(uint4 a) {
    return make_uint4(a.x << 2, __funnelshift_l(a.x, a.y, 2),
                      __funnelshift_l(a.y, a.z, 2), __funnelshift_l(a.z, a.w, 2));
}
__device__ __forceinline__ uint4 shr2(uint4 a) {
    return make_uint4(__funnelshift_r(a.x, a.y, 2), __funnelshift_r(a.y, a.z, 2),
                      __funnelshift_r(a.z, a.w, 2), a.w >> 2);
}

// ---------- Pass 1: bit-pack targets (coalesced loads + smem nibble transpose) ----------
__global__ void __launch_bounds__(256)
pack_kernel(const float* __restrict__ targets,
            const unsigned int* __restrict__ mask)
{
    if (blockIdx.x == 0 && threadIdx.x == 0) { g_sum = 0.0; g_cnt = 0.0; g_done = 0u; }

    unsigned p = blockIdx.x;
    int slab = p >> 8;                               // 0..7 (block-uniform)
    int b = slab >> 2;
    int ch = ((slab & 3) << 1) + 1;
    if (mask[b * CDIM + ch] == 0u) return;           // inactive: never read

    __shared__ __align__(8) unsigned char nib[2048];
    unsigned t = threadIdx.x;
    size_t base = ((size_t)(b * CDIM + ch) << 21) + ((size_t)(p & 255u) << 13);
    const float4* src = (const float4*)(targets + base);

    #pragma unroll
    for (int i = 0; i < 8; ++i) {                    // coalesced: lanes adjacent
        float4 v = __ldg(src + i * 256 + t);
        unsigned n = (v.x > 0.5f ? 1u : 0u) | (v.y > 0.5f ? 2u : 0u)
                   | (v.z > 0.5f ? 4u : 0u) | (v.w > 0.5f ? 8u : 0u);
        nib[i * 256 + t] = (unsigned char)n;
    }
    __syncthreads();

    uint2 q = *(const uint2*)(nib + 8 * t);          // 8 nibbles (bytes) for this word
    unsigned x = q.x; x = (x | (x >> 4)) & 0x00FF00FFu; x = (x | (x >> 8)) & 0x0000FFFFu;
    unsigned y = q.y; y = (y | (y >> 4)) & 0x00FF00FFu; y = (y | (y >> 8)) & 0x0000FFFFu;
    ((unsigned*)g_pack)[p * 256u + t] = x | (y << 16);
}

// ---------- Pass 1.5: double 6-conn erosion of the bitmask (one row per thread) ----------
__global__ void __launch_bounds__(256)
erode_kernel(const unsigned int* __restrict__ mask)
{
    unsigned j = blockIdx.x * 256u + threadIdx.x;    // < 2^17
    int slab = j >> 14;
    int b = slab >> 2;
    int ch = ((slab & 3) << 1) + 1;
    if (mask[b * CDIM + ch] == 0u) return;

    int rr = j & (ROWS_PER_SLAB - 1);
    int d = rr >> 7, h = rr & 127;

    uint4 e = make_uint4(0, 0, 0, 0);
    if (d >= 2 && d <= 125 && h >= 2 && h <= 125) {
        const uint4* pk = g_pack + slab * ROWS_PER_SLAB;
        uint4 m00 = __ldg(pk + rr);
        uint4 a0 = __ldg(pk + rr + 256), a1 = __ldg(pk + rr - 256);
        uint4 a2 = __ldg(pk + rr + 2),   a3 = __ldg(pk + rr - 2);
        uint4 a4 = __ldg(pk + rr + 129), a5 = __ldg(pk + rr + 127);
        uint4 a6 = __ldg(pk + rr - 127), a7 = __ldg(pk + rr - 129);
        uint4 a8 = __ldg(pk + rr + 128), a9 = __ldg(pk + rr - 128);
        uint4 aA = __ldg(pk + rr + 1),   aB = __ldg(pk + rr - 1);

        uint4 R = band(band(band(a0, a1), band(a2, a3)),
                       band(band(a4, a5), band(a6, a7)));
        uint4 q = band(band(a8, a9), band(aA, aB));
        uint4 u = band(m00, q);
        e = band(band(band(R, m00), u), band(shl1(u), shr1(u)));
        e = band(e, band(shl2(m00), shr2(m00)));
    }
    g_er[slab * ROWS_PER_SLAB + rr] = e;
}

// ---------- Pass 2: BCE + weights + reduction + fused finalize ----------
// Warp = 4 consecutive rows. Lane l: row = l>>3, sub-slot s = l&7, owns the
// four float4 chunks at w = s*4 + 32*j (j=0..3). Every LDG.128 is fully
// coalesced (8 consecutive float4 per row-group x 4 rows = 4 lines).
__global__ void __launch_bounds__(256)
loss_kernel(const float* __restrict__ logits,
            const unsigned int* __restrict__ mask,
            const float* __restrict__ spatial,
            float* __restrict__ out)
{
    unsigned tid = blockIdx.x * 256u + threadIdx.x;    // < 2^20
    unsigned gw = tid >> 5;                            // global warp id, < 2^15
    int slab = gw >> 12;                               // 4096 warps per slab
    int b = slab >> 2;
    int ch = ((slab & 3) << 1) + 1;

    float vsum = 0.0f, csum = 0.0f;

    if (mask[b * CDIM + ch] != 0u) {                   // warp-uniform L1 scalar
        int lane = tid & 31;
        int s = lane & 7;                              // sub-slot
        int rr = ((gw & 4095) << 2) + (lane >> 3);     // row d*128+h
        int wbase = s << 2;                            // s*4

        size_t lix = ((size_t)(b * CDIM + ch) << 21) + ((size_t)rr << 7) + wbase;
        unsigned six = ((unsigned)b << 21) + ((unsigned)rr << 7) + wbase;

        // 10 independent loads up front (all coalesced / broadcast)
        float4 lg0 = __ldg((const float4*)(logits + lix));
        float4 lg1 = __ldg((const float4*)(logits + lix + 32));
        float4 lg2 = __ldg((const float4*)(logits + lix + 64));
        float4 lg3 = __ldg((const float4*)(logits + lix + 96));
        float4 sm0 = __ldg((const float4*)(spatial + six));
        float4 sm1 = __ldg((const float4*)(spatial + six + 32));
        float4 sm2 = __ldg((const float4*)(spatial + six + 64));
        float4 sm3 = __ldg((const float4*)(spatial + six + 96));
        uint4 m00 = __ldg(g_pack + slab * ROWS_PER_SLAB + rr);
        uint4 e00 = __ldg(g_er   + slab * ROWS_PER_SLAB + rr);

        int sh = s << 2;                               // nibble shift
        unsigned tw0 = (m00.x >> sh) & 0xFu, eb0 = (e00.x >> sh) & 0xFu;
        unsigned tw1 = (m00.y >> sh) & 0xFu, eb1 = (e00.y >> sh) & 0xFu;
        unsigned tw2 = (m00.z >> sh) & 0xFu, eb2 = (e00.z >> sh) & 0xFu;
        unsigned tw3 = (m00.w >> sh) & 0xFu, eb3 = (e00.w >> sh) & 0xFu;

        const float4 lgs[4] = {lg0, lg1, lg2, lg3};
        const float4 sms[4] = {sm0, sm1, sm2, sm3};
        const unsigned tws[4] = {tw0, tw1, tw2, tw3};
        const unsigned bbs[4] = {tw0 & ~eb0, tw1 & ~eb1, tw2 & ~eb2, tw3 & ~eb3};

        #pragma unroll
        for (int j = 0; j < 4; ++j) {
            #pragma unroll
            for (int k = 0; k < 4; ++k) {
                float l = (k == 0) ? lgs[j].x : (k == 1) ? lgs[j].y : (k == 2) ? lgs[j].z : lgs[j].w;
                float sp = (k == 0) ? sms[j].x : (k == 1) ? sms[j].y : (k == 2) ? sms[j].z : sms[j].w;
                unsigned tb = (tws[j] >> k) & 1u;
                // max(l,0) - l*t == max(sflip, 0) with sflip = t ? -l : l
                float sflip = __uint_as_float(__float_as_uint(l) ^ (tb << 31));
                float u = __expf(-fabsf(l));
                float bce = fmaxf(sflip, 0.0f) + __logf(1.0f + u);
                float wgt = ((bbs[j] >> k) & 1u) ? 5.0f : 1.0f;
                vsum += bce * wgt * sp;
                csum += sp;
            }
        }
    }

    // warp reduce
    #pragma unroll
    for (int off = 16; off > 0; off >>= 1) {
        vsum += __shfl_down_sync(0xFFFFFFFFu, vsum, off);
        csum += __shfl_down_sync(0xFFFFFFFFu, csum, off);
    }
    __shared__ float s_v[8], s_c[8];
    int lane = threadIdx.x & 31, wid = threadIdx.x >> 5;
    if (lane == 0) { s_v[wid] = vsum; s_c[wid] = csum; }
    __syncthreads();
    if (wid == 0) {
        vsum = (lane < 8) ? s_v[lane] : 0.0f;
        csum = (lane < 8) ? s_c[lane] : 0.0f;
        #pragma unroll
        for (int off = 4; off > 0; off >>= 1) {
            vsum += __shfl_down_sync(0xFFFFFFFFu, vsum, off);
            csum += __shfl_down_sync(0xFFFFFFFFu, csum, off);
        }
        if (lane == 0) {
            if (vsum != 0.0f) atomicAdd(&g_sum, (double)vsum);
            if (csum != 0.0f) atomicAdd(&g_cnt, (double)csum);
            __threadfence();
            unsigned ticket = atomicAdd(&g_done, 1u);
            if (ticket == NBLK2 - 1u) {              // last block finalizes
                double n = g_cnt;
                double s = g_sum;
                out[0] = (n > 0.0) ? (float)(s / (n > 1.0 ? n : 1.0)) : 0.0f;
            }
        }
    }
}

extern "C" void kernel_launch(void* const* d_in, const int* in_sizes, int n_in,
                              void* d_out, int out_size) {
    const float*        logits  = (const float*)d_in[0];
    const float*        targets = (const float*)d_in[1];
    const unsigned int* mask    = (const unsigned int*)d_in[2];
    const float*        spatial = (const float*)d_in[3];
    float*              out     = (float*)d_out;

    pack_kernel<<<NPACK_BLOCKS, 256>>>(targets, mask);
    erode_kernel<<<NERODE / 256, 256>>>(mask);
    loss_kernel<<<NBLK2, 256>>>(logits, mask, spatial, out);
}